// round 17
// baseline (speedup 1.0000x reference)
#include <cuda_runtime.h>
#include <cuda_fp16.h>
#include <math.h>
#include <stdint.h>

// Problem constants
#define BB 16
#define NN 1024
#define LL 313
#define NL 1337          // N + L
#define CC 768
#define HH 12
#define DH 64
#define MLPD 3072
#define LN_EPS 1e-5f
#define MW 44            // mask words per row, padded (ceil(1337/32)=42, +2 pad)

// ---------------------------------------------------------------------------
// Scratch (device globals; no runtime allocation allowed)
// ---------------------------------------------------------------------------
__device__ __half g_xn_h    [(size_t)BB * NN * CC];   // ln1(x) fp16 (GEMM A + residual)
__device__ __half g_x1_h    [(size_t)BB * NN * CC];   // x1 fp16 (LN2 input + residual)
__device__ __half g_tokens_h[(size_t)BB * NL * CC];
__device__ __half g_q_h     [(size_t)BB * NN * CC];
__device__ __half g_k_h     [(size_t)BB * NL * CC];
__device__ __half g_v_h     [(size_t)BB * NL * CC];
__device__ __half g_attn_h  [(size_t)BB * NN * CC];
__device__ __half g_h_h     [(size_t)BB * NN * CC];
__device__ __half g_mlp_h   [(size_t)BB * NN * MLPD];
__device__ __half g_wq_h [(size_t)CC * CC];          // weights [N][K] (transposed)
__device__ __half g_wk_h [(size_t)CC * CC];
__device__ __half g_wv_h [(size_t)CC * CC];
__device__ __half g_wp_h [(size_t)CC * CC];
__device__ __half g_w1_h [(size_t)CC * MLPD];
__device__ __half g_w2_h [(size_t)MLPD * CC];
__device__ uint32_t g_mbits[(size_t)BB * NN * MW];

// ---------------------------------------------------------------------------
// Helpers
// ---------------------------------------------------------------------------
__device__ __forceinline__ uint32_t smem_u32(const void* p) {
    uint32_t a;
    asm("{ .reg .u64 t; cvta.to.shared.u64 t, %1; cvt.u32.u64 %0, t; }" : "=r"(a) : "l"(p));
    return a;
}

#define CP_ASYNC16(saddr, gptr) \
    asm volatile("cp.async.cg.shared.global [%0], [%1], 16;" :: "r"(saddr), "l"(gptr))
#define CP_COMMIT() asm volatile("cp.async.commit_group;" ::: "memory")
#define CP_WAIT1()  asm volatile("cp.async.wait_group 1;" ::: "memory")
#define CP_WAIT0()  asm volatile("cp.async.wait_group 0;" ::: "memory")

// fp16 m16n8k16 with fp32 accum
__device__ __forceinline__ void mma_f16(float* d, const uint32_t* a, const uint32_t* b) {
    asm volatile(
        "mma.sync.aligned.m16n8k16.row.col.f32.f16.f16.f32 "
        "{%0,%1,%2,%3}, {%4,%5,%6,%7}, {%8,%9}, {%0,%1,%2,%3};"
        : "+f"(d[0]), "+f"(d[1]), "+f"(d[2]), "+f"(d[3])
        : "r"(a[0]), "r"(a[1]), "r"(a[2]), "r"(a[3]), "r"(b[0]), "r"(b[1]));
}

__device__ __forceinline__ void ldsm_x4(uint32_t* r, uint32_t addr) {
    asm volatile("ldmatrix.sync.aligned.m8n8.x4.shared.b16 {%0,%1,%2,%3}, [%4];"
                 : "=r"(r[0]), "=r"(r[1]), "=r"(r[2]), "=r"(r[3]) : "r"(addr));
}
__device__ __forceinline__ void ldsm_x4_t(uint32_t* r, uint32_t addr) {
    asm volatile("ldmatrix.sync.aligned.m8n8.x4.trans.shared.b16 {%0,%1,%2,%3}, [%4];"
                 : "=r"(r[0]), "=r"(r[1]), "=r"(r[2]), "=r"(r[3]) : "r"(addr));
}

// Fast GELU: tanh-form with hardware tanh.approx.f32
__device__ __forceinline__ float gelu_fast(float x) {
    float t = 0.7978845608028654f * (x + 0.044715f * x * x * x);
    float th;
    asm("tanh.approx.f32 %0, %1;" : "=f"(th) : "f"(t));
    return 0.5f * x * (1.0f + th);
}

// ---------------------------------------------------------------------------
// Fused pre-pass: weight converts + LN1 + color copy + mask pack, ONE launch.
// ---------------------------------------------------------------------------
#define CV_TILES 6912
#define LN_ROWS (BB * NN)        // 16384
#define CP_BLOCKS 1878           // 480768 vec8 ops / 256
#define PK_BLOCKS 2048           // 16384 rows / 8 warps per block
#define PRE_GRID (CV_TILES + LN_ROWS + CP_BLOCKS + PK_BLOCKS)

__global__ void pre_kernel(const float* __restrict__ x,
                           const float* __restrict__ ln1_g,
                           const float* __restrict__ ln1_b,
                           const float* __restrict__ ce,
                           const int* __restrict__ mask,
                           const float* __restrict__ Wq, const float* __restrict__ Wk,
                           const float* __restrict__ Wv, const float* __restrict__ Wp,
                           const float* __restrict__ W1, const float* __restrict__ W2) {
    __shared__ float shm[32 * 33];
    const int bid = blockIdx.x;
    const int tid = threadIdx.x;

    if (bid < CV_TILES) {
        // ---- weight transpose tile ----
        const float* src; __half* dst; int K, N, rel;
        if (bid < 576)       { src = Wq; dst = g_wq_h; K = CC; N = CC;  rel = bid; }
        else if (bid < 1152) { src = Wk; dst = g_wk_h; K = CC; N = CC;  rel = bid - 576; }
        else if (bid < 1728) { src = Wv; dst = g_wv_h; K = CC; N = CC;  rel = bid - 1152; }
        else if (bid < 2304) { src = Wp; dst = g_wp_h; K = CC; N = CC;  rel = bid - 1728; }
        else if (bid < 4608) { src = W1; dst = g_w1_h; K = CC; N = MLPD; rel = bid - 2304; }
        else                 { src = W2; dst = g_w2_h; K = MLPD; N = CC; rel = bid - 4608; }
        int ntN = N / 32;
        int n0 = (rel % ntN) * 32;
        int k0 = (rel / ntN) * 32;
        int tx = tid & 31, ty = tid >> 5;
        float (*t)[33] = (float(*)[33])shm;
#pragma unroll
        for (int i = 0; i < 32; i += 8)
            t[ty + i][tx] = src[(size_t)(k0 + ty + i) * N + n0 + tx];
        __syncthreads();
#pragma unroll
        for (int i = 0; i < 32; i += 8)
            dst[(size_t)(n0 + ty + i) * K + k0 + tx] = __float2half(t[tx][ty + i]);
        return;
    }

    if (bid < CV_TILES + LN_ROWS) {
        // ---- LN1 row (fp16 outputs only) ----
        int row = bid - CV_TILES;
        const float* xr = x + (size_t)row * CC;
        float v[3];
        float s1 = 0.f, s2 = 0.f;
#pragma unroll
        for (int i = 0; i < 3; ++i) {
            v[i] = xr[tid + 256 * i];
            s1 += v[i];
            s2 += v[i] * v[i];
        }
#pragma unroll
        for (int off = 16; off; off >>= 1) {
            s1 += __shfl_xor_sync(0xffffffffu, s1, off);
            s2 += __shfl_xor_sync(0xffffffffu, s2, off);
        }
        int w = tid >> 5;
        if ((tid & 31) == 0) { shm[w] = s1; shm[8 + w] = s2; }
        __syncthreads();
        if (tid == 0) {
            float a = 0.f, b2 = 0.f;
#pragma unroll
            for (int i = 0; i < 8; ++i) { a += shm[i]; b2 += shm[8 + i]; }
            float mu = a * (1.0f / CC);
            float var = b2 * (1.0f / CC) - mu * mu;
            shm[16] = mu;
            shm[17] = rsqrtf(var + LN_EPS);
        }
        __syncthreads();
        float mu = shm[16], rstd = shm[17];

        __half* orowH = g_xn_h + (size_t)row * CC;
        int b = row / NN, n = row % NN;
        __half* trow = g_tokens_h + ((size_t)b * NL + n) * CC;
#pragma unroll
        for (int i = 0; i < 3; ++i) {
            int c = tid + 256 * i;
            float y = (v[i] - mu) * rstd * ln1_g[c] + ln1_b[c];
            __half yh = __float2half(y);
            orowH[c] = yh;
            trow[c] = yh;
        }
        return;
    }

    if (bid < CV_TILES + LN_ROWS + CP_BLOCKS) {
        // ---- color copy: 8 halves per thread, vectorized ----
        int idx = (bid - CV_TILES - LN_ROWS) * 256 + tid;   // 0..480767
        int e = idx * 8;
        int b = e / (LL * CC);
        int r = e % (LL * CC);
        float4 v0 = *(const float4*)(ce + e);
        float4 v1 = *(const float4*)(ce + e + 4);
        __half2 p0 = __floats2half2_rn(v0.x, v0.y);
        __half2 p1 = __floats2half2_rn(v0.z, v0.w);
        __half2 p2 = __floats2half2_rn(v1.x, v1.y);
        __half2 p3 = __floats2half2_rn(v1.z, v1.w);
        uint4 u;
        u.x = *(uint32_t*)&p0; u.y = *(uint32_t*)&p1;
        u.z = *(uint32_t*)&p2; u.w = *(uint32_t*)&p3;
        *(uint4*)(g_tokens_h + ((size_t)b * NL + NN) * CC + r) = u;
        return;
    }

    {
        // ---- mask pack: warp-ballot, one warp per row, coalesced reads ----
        // words 42,43 are zero padding (cols >= NL)
        int warp = (bid - CV_TILES - LN_ROWS - CP_BLOCKS) * 8 + (tid >> 5);
        int lane = tid & 31;
        const int* mrow = mask + (size_t)warp * NL;
        uint32_t* orow = g_mbits + (size_t)warp * MW;
#pragma unroll 4
        for (int wd = 0; wd < MW; ++wd) {
            int col = wd * 32 + lane;
            int val = (col < NL) ? mrow[col] : 0;
            uint32_t bits = __ballot_sync(0xffffffffu, val != 0);
            if (lane == 0) orow[wd] = bits;
        }
    }
}

// ---------------------------------------------------------------------------
// fp16 tensor-core GEMM — BK=64, 3-stage cp.async, ldmatrix A+B (proven R11).
// EPI: 0 = bias, 1 = bias + fp16 residual, 2 = bias + fast GELU
// MODE 0: normal. MODE 2: QKV-fused (grid.x = 3 col segments).
// ---------------------------------------------------------------------------
#define HA_STRIDE 72                         // halves per row (64 + 8 pad)
#define HROW_B (HA_STRIDE * 2)               // 144 bytes per row
#define HA_BYTES (128 * HROW_B)              // 18432
#define HBUF_BYTES (2 * HA_BYTES)            // 36864
#define NSTAGE 3
#define GEMM_SMEM (NSTAGE * HBUF_BYTES)      // 110592

template <int EPI, int MODE>
__global__ __launch_bounds__(256, 2)
void gemm_h(const __half* __restrict__ A,
            const __half* __restrict__ A2,
            const __half* __restrict__ Wt,
            const float* __restrict__ bias,
            const __half* __restrict__ Wt2,
            const float* __restrict__ bias2,
            const __half* __restrict__ Wt3,
            const float* __restrict__ bias3,
            const __half* __restrict__ res,
            float* __restrict__ OutF,
            __half* __restrict__ OutH,
            __half* __restrict__ OutH2,
            __half* __restrict__ OutH3,
            int M, int M2, int K, int Nc) {
    extern __shared__ __align__(16) char dyn[];

    const int tid = threadIdx.x;
    const int w = tid >> 5;
    const int lane = tid & 31;
    const int warpRow = w >> 2;
    const int warpCol = w & 3;
    const int rowBase = blockIdx.y * 128;
    const int colTiles = Nc >> 7;
    int cx = blockIdx.x;
    const __half* Au = A;
    const __half* Wu = Wt;
    const float* bu = bias;
    __half* OH = OutH;
    int Mu = M;
    if (MODE == 2) {
        int seg = cx / colTiles;
        cx -= seg * colTiles;
        if (seg == 0)      { Au = A2; Mu = M2; }
        else if (seg == 1) { Wu = Wt2; bu = bias2; OH = OutH2; }
        else               { Wu = Wt3; bu = bias3; OH = OutH3; }
        if (rowBase >= Mu) return;
    }
    const int colBase = cx * 128;
    const int nk = K >> 6;                   // K / 64

    const uint32_t sbase = smem_u32(dyn);
    const int g = lane >> 2;
    const int t4 = lane & 3;
    const int lane7 = lane & 7;
    const int half8 = (lane >> 3) & 1;
    const int quad  = lane >> 4;

    auto load_chunk = [&](int buf, int k0) {
        uint32_t aB = sbase + buf * HBUF_BYTES;
        uint32_t bB = aB + HA_BYTES;
#pragma unroll
        for (int j = 0; j < 4; ++j) {
            int idx = tid + 256 * j;
            int m = idx >> 3, seg = idx & 7;
            int row = rowBase + m; if (row >= Mu) row = Mu - 1;
            const __half* src = Au + (size_t)row * K + k0 + seg * 8;
            CP_ASYNC16(aB + (uint32_t)(m * HROW_B + seg * 16), src);
        }
#pragma unroll
        for (int j = 0; j < 4; ++j) {
            int idx = tid + 256 * j;
            int n = idx >> 3, seg = idx & 7;
            const __half* src = Wu + (size_t)(colBase + n) * K + k0 + seg * 8;
            CP_ASYNC16(bB + (uint32_t)(n * HROW_B + seg * 16), src);
        }
    };

    float acc[4][4][4];
#pragma unroll
    for (int i = 0; i < 4; ++i)
#pragma unroll
        for (int j = 0; j < 4; ++j)
#pragma unroll
            for (int r = 0; r < 4; ++r) acc[i][j][r] = 0.f;

    load_chunk(0, 0); CP_COMMIT();
    load_chunk(1, 64); CP_COMMIT();

    int buf = 0;
    for (int i = 0; i < nk; ++i) {
        CP_WAIT1();
        __syncthreads();

        const uint32_t aFragBase = sbase + buf * HBUF_BYTES
                                 + (uint32_t)((warpRow * 64 + lane7 + half8 * 8) * HROW_B)
                                 + quad * 16;
        const uint32_t bFragBase = sbase + buf * HBUF_BYTES + HA_BYTES
                                 + (uint32_t)((warpCol * 32 + lane7 + quad * 8) * HROW_B)
                                 + half8 * 16;

#pragma unroll
        for (int kk = 0; kk < 4; ++kk) {
            uint32_t af[4][4];
#pragma unroll
            for (int mt = 0; mt < 4; ++mt)
                ldsm_x4(af[mt], aFragBase + (uint32_t)(mt * 16 * HROW_B + kk * 32));
            uint32_t bf[2][4];
            ldsm_x4(bf[0], bFragBase + (uint32_t)(kk * 32));
            ldsm_x4(bf[1], bFragBase + (uint32_t)(16 * HROW_B + kk * 32));
#pragma unroll
            for (int mt = 0; mt < 4; ++mt)
#pragma unroll
                for (int ntp = 0; ntp < 2; ++ntp) {
                    mma_f16(acc[mt][2 * ntp],     af[mt], bf[ntp]);
                    mma_f16(acc[mt][2 * ntp + 1], af[mt], bf[ntp] + 2);
                }
        }

        if (i + 2 < nk) load_chunk((buf + 2) % NSTAGE, (i + 2) * 64);
        CP_COMMIT();
        buf = (buf + 1) % NSTAGE;
    }

    // ---- epilogue ----
#pragma unroll
    for (int mt = 0; mt < 4; ++mt) {
#pragma unroll
        for (int half = 0; half < 2; ++half) {
            int row = rowBase + warpRow * 64 + mt * 16 + half * 8 + g;
            if (row >= Mu) continue;
#pragma unroll
            for (int nt = 0; nt < 4; ++nt) {
                int col = colBase + warpCol * 32 + nt * 8 + t4 * 2;
                float v0 = acc[mt][nt][half * 2 + 0] + bu[col];
                float v1 = acc[mt][nt][half * 2 + 1] + bu[col + 1];
                if (EPI == 1) {
                    __half2 rh = *(const __half2*)(res + (size_t)row * Nc + col);
                    float2 rf = __half22float2(rh);
                    v0 += rf.x; v1 += rf.y;
                }
                if (EPI == 2) {
                    v0 = gelu_fast(v0);
                    v1 = gelu_fast(v1);
                }
                if (OutF) *(float2*)(OutF + (size_t)row * Nc + col) = make_float2(v0, v1);
                if (OH)   *(__half2*)(OH + (size_t)row * Nc + col) = __floats2half2_rn(v0, v1);
            }
        }
    }
}

// ---------------------------------------------------------------------------
// LayerNorm (LN2): fp16 in, fp16 out
// ---------------------------------------------------------------------------
__global__ void ln_kernel(const __half* __restrict__ in,
                          const float* __restrict__ gam,
                          const float* __restrict__ bet,
                          __half* __restrict__ outH) {
    int row = blockIdx.x;
    const __half* xr = in + (size_t)row * CC;
    int tid = threadIdx.x;

    float v[3];
    float s1 = 0.f, s2 = 0.f;
#pragma unroll
    for (int i = 0; i < 3; ++i) {
        v[i] = __half2float(xr[tid + 256 * i]);
        s1 += v[i];
        s2 += v[i] * v[i];
    }
#pragma unroll
    for (int off = 16; off; off >>= 1) {
        s1 += __shfl_xor_sync(0xffffffffu, s1, off);
        s2 += __shfl_xor_sync(0xffffffffu, s2, off);
    }
    __shared__ float sm1[8], sm2[8];
    __shared__ float s_mu, s_rstd;
    int w = tid >> 5;
    if ((tid & 31) == 0) { sm1[w] = s1; sm2[w] = s2; }
    __syncthreads();
    if (tid == 0) {
        float a = 0.f, b2 = 0.f;
#pragma unroll
        for (int i = 0; i < 8; ++i) { a += sm1[i]; b2 += sm2[i]; }
        float mu = a * (1.0f / CC);
        float var = b2 * (1.0f / CC) - mu * mu;
        s_mu = mu;
        s_rstd = rsqrtf(var + LN_EPS);
    }
    __syncthreads();
    float mu = s_mu, rstd = s_rstd;

    __half* orowH = outH + (size_t)row * CC;
#pragma unroll
    for (int i = 0; i < 3; ++i) {
        int c = tid + 256 * i;
        float y = (v[i] - mu) * rstd * gam[c] + bet[c];
        orowH[c] = __float2half(y);
    }
}

// ---------------------------------------------------------------------------
// fp16 flash attention, fixed-shift softmax, 128-key chunks (2x64 subtiles).
// SMEM: Q[128*72] + K[2][128*72] + V[2][128*72] + P[8][16*72] = 110592 B.
// ---------------------------------------------------------------------------
#define QS 72
#define KVS 72
#define Q_HALVES (128 * QS)
#define KV2_HALVES (128 * KVS)               // per stage (128 tokens)
#define KV2_BYTES (KV2_HALVES * 2)           // 18432
#define ATTH_SMEM ((Q_HALVES + 4 * KV2_HALVES + 8 * 16 * KVS) * 2)  // 110592 B
#define ATT_NC2 11                           // ceil(1337/128)

__global__ __launch_bounds__(256, 2)
void attn_h16(const uint32_t* __restrict__ mbits) {
    extern __shared__ __align__(16) __half hsm[];
    const int b = blockIdx.z, h = blockIdx.y, qt = blockIdx.x;
    const int tid = threadIdx.x;
    const int w = tid >> 5, lane = tid & 31;
    const int g = lane >> 2, t4 = lane & 3;
    const int lane7 = lane & 7;
    const int half8 = (lane >> 3) & 1;
    const int quad  = lane >> 4;

    __half* Qs = hsm;
    __half* Ks = hsm + Q_HALVES;
    __half* Vs = Ks + 2 * KV2_HALVES;
    __half* Ps = Vs + 2 * KV2_HALVES + w * (16 * KVS);
    const uint32_t q_addr  = smem_u32(Qs);
    const uint32_t k_addr  = smem_u32(Ks);
    const uint32_t v_addr  = smem_u32(Vs);
    const uint32_t p_addr  = smem_u32(Ps);

    {
        const __half* qg = g_q_h + ((size_t)(b * NN + qt * 128)) * CC + h * DH;
#pragma unroll
        for (int j = 0; j < 4; ++j) {
            int idx = tid + 256 * j;
            int row = idx >> 3, seg = idx & 7;
            CP_ASYNC16(q_addr + (uint32_t)(row * QS + seg * 8) * 2,
                       qg + (size_t)row * CC + seg * 8);
        }
    }

    // 128-token chunk loader: 2048 segs / 256 thr = 8 per thread (4 K + 4 V)
    auto load_kv = [&](int buf, int kb) {
        int j = tid >> 1;              // token 0..127
        int s0 = (tid & 1) * 4;        // seg base 0 or 4
        int tok = kb + j; if (tok >= NL) tok = NL - 1;
        const __half* ksrc = g_k_h + ((size_t)b * NL + tok) * CC + h * DH;
        const __half* vsrc = g_v_h + ((size_t)b * NL + tok) * CC + h * DH;
        uint32_t off = (uint32_t)(buf * KV2_HALVES + j * KVS) * 2;
#pragma unroll
        for (int it = 0; it < 4; ++it) {
            int seg = s0 + it;
            CP_ASYNC16(k_addr + off + seg * 16, ksrc + seg * 8);
            CP_ASYNC16(v_addr + off + seg * 16, vsrc + seg * 8);
        }
    };

    const uint32_t* mrow0 = mbits + (size_t)(b * NN + qt * 128 + w * 16 + g) * MW;
    const uint32_t* mrow1 = mrow0 + (size_t)8 * MW;

    float l0 = 0.f, l1 = 0.f;
    float o[8][4];
#pragma unroll
    for (int nt = 0; nt < 8; ++nt)
#pragma unroll
        for (int r = 0; r < 4; ++r) o[nt][r] = 0.f;

    uint32_t aq[4][4];

    load_kv(0, 0); CP_COMMIT();    // group: Q + KV chunk 0

    for (int c = 0; c < ATT_NC2; ++c) {
        if (c + 1 < ATT_NC2) load_kv((c + 1) & 1, (c + 1) * 128);
        CP_COMMIT();
        if (c + 1 < ATT_NC2) { CP_WAIT1(); } else { CP_WAIT0(); }
        __syncthreads();

        if (c == 0) {
            const uint32_t qf = q_addr + (uint32_t)((w * 16 + lane7 + half8 * 8) * QS) * 2
                              + quad * 16;
            const __half2 sc = __float2half2_rn(0.125f);   // 1/sqrt(DH), exact
#pragma unroll
            for (int kk = 0; kk < 4; ++kk) {
                ldsm_x4(aq[kk], qf + kk * 32);
#pragma unroll
                for (int i2 = 0; i2 < 4; ++i2) {
                    __half2 qv = __hmul2(*(__half2*)&aq[kk][i2], sc);
                    aq[kk][i2] = *(uint32_t*)&qv;
                }
            }
        }

        const uint32_t KbC = k_addr + (c & 1) * KV2_BYTES;
        const uint32_t VbC = v_addr + (c & 1) * KV2_BYTES;

#pragma unroll
        for (int hc = 0; hc < 2; ++hc) {
            const uint32_t Kb = KbC + hc * (64 * KVS * 2);
            const uint32_t Vb = VbC + hc * (64 * KVS * 2);
            const int wb = c * 4 + hc * 2;
            const uint32_t mw00 = mrow0[wb], mw01 = mrow0[wb + 1];
            const uint32_t mw10 = mrow1[wb], mw11 = mrow1[wb + 1];

            float s[8][4];
#pragma unroll
            for (int nt = 0; nt < 8; ++nt)
                s[nt][0] = s[nt][1] = s[nt][2] = s[nt][3] = 0.f;
#pragma unroll
            for (int p = 0; p < 4; ++p) {
                const uint32_t kf = Kb + (uint32_t)((p * 16 + lane7 + quad * 8) * KVS) * 2
                                  + half8 * 16;
#pragma unroll
                for (int kk = 0; kk < 4; ++kk) {
                    uint32_t kb4[4];
                    ldsm_x4(kb4, kf + kk * 32);
                    mma_f16(s[2 * p],     aq[kk], kb4);
                    mma_f16(s[2 * p + 1], aq[kk], kb4 + 2);
                }
            }

            // fixed-shift softmax: p = exp(s) (masked -> 0), accumulate l
            float rs0 = 0.f, rs1 = 0.f;
#pragma unroll
            for (int nt = 0; nt < 8; ++nt) {
                int colb = nt * 8 + t4 * 2;
                uint32_t wr0 = (colb < 32) ? mw00 : mw01;
                uint32_t wr1 = (colb < 32) ? mw10 : mw11;
                int sh = colb & 31;
                float p0 = ((wr0 >> sh) & 1u)       ? __expf(s[nt][0]) : 0.f;
                float p1 = ((wr0 >> (sh + 1)) & 1u) ? __expf(s[nt][1]) : 0.f;
                float p2 = ((wr1 >> sh) & 1u)       ? __expf(s[nt][2]) : 0.f;
                float p3 = ((wr1 >> (sh + 1)) & 1u) ? __expf(s[nt][3]) : 0.f;
                rs0 += p0 + p1; rs1 += p2 + p3;
                *(__half2*)&Ps[g * KVS + colb]       = __floats2half2_rn(p0, p1);
                *(__half2*)&Ps[(8 + g) * KVS + colb] = __floats2half2_rn(p2, p3);
            }
            rs0 += __shfl_xor_sync(0xffffffffu, rs0, 1);
            rs0 += __shfl_xor_sync(0xffffffffu, rs0, 2);
            rs1 += __shfl_xor_sync(0xffffffffu, rs1, 1);
            rs1 += __shfl_xor_sync(0xffffffffu, rs1, 2);
            l0 += rs0;
            l1 += rs1;
            __syncwarp();

            const uint32_t pf = p_addr + (uint32_t)((lane7 + half8 * 8) * KVS) * 2 + quad * 16;
#pragma unroll
            for (int kk2 = 0; kk2 < 4; ++kk2) {
                uint32_t ap[4];
                ldsm_x4(ap, pf + kk2 * 32);
                const uint32_t vfRow = Vb
                    + (uint32_t)((kk2 * 16 + lane7 + half8 * 8) * KVS) * 2 + quad * 16;
#pragma unroll
                for (int dp = 0; dp < 4; ++dp) {
                    uint32_t vb4[4];
                    ldsm_x4_t(vb4, vfRow + dp * 32);
                    mma_f16(o[2 * dp],     ap, vb4);
                    mma_f16(o[2 * dp + 1], ap, vb4 + 2);
                }
            }
            __syncwarp();
        }
        __syncthreads();
    }

    {
        float inv0 = 1.0f / l0, inv1 = 1.0f / l1;
        __half* ob = g_attn_h + ((size_t)(b * NN + qt * 128 + w * 16)) * CC + h * DH;
#pragma unroll
        for (int nt = 0; nt < 8; ++nt) {
            int col = nt * 8 + t4 * 2;
            *(__half2*)(ob + (size_t)g * CC + col) =
                __floats2half2_rn(o[nt][0] * inv0, o[nt][1] * inv0);
            *(__half2*)(ob + (size_t)(8 + g) * CC + col) =
                __floats2half2_rn(o[nt][2] * inv1, o[nt][3] * inv1);
        }
    }
}

// ---------------------------------------------------------------------------
// Launch
// ---------------------------------------------------------------------------
extern "C" void kernel_launch(void* const* d_in, const int* in_sizes, int n_in,
                              void* d_out, int out_size) {
    const float* x     = (const float*)d_in[0];
    const float* ce    = (const float*)d_in[1];
    const int*   mask  = (const int*)  d_in[2];
    const float* ln1_g = (const float*)d_in[3];
    const float* ln1_b = (const float*)d_in[4];
    const float* ln2_g = (const float*)d_in[5];
    const float* ln2_b = (const float*)d_in[6];
    const float* Wq = (const float*)d_in[7];
    const float* bq = (const float*)d_in[8];
    const float* Wk = (const float*)d_in[9];
    const float* bk = (const float*)d_in[10];
    const float* Wv = (const float*)d_in[11];
    const float* bv = (const float*)d_in[12];
    const float* Wp = (const float*)d_in[13];
    const float* bp = (const float*)d_in[14];
    const float* W1 = (const float*)d_in[15];
    const float* b1 = (const float*)d_in[16];
    const float* W2 = (const float*)d_in[17];
    const float* b2 = (const float*)d_in[18];
    float* out = (float*)d_out;

    cudaFuncSetAttribute(gemm_h<0,2>, cudaFuncAttributeMaxDynamicSharedMemorySize, GEMM_SMEM);
    cudaFuncSetAttribute(gemm_h<1,0>, cudaFuncAttributeMaxDynamicSharedMemorySize, GEMM_SMEM);
    cudaFuncSetAttribute(gemm_h<2,0>, cudaFuncAttributeMaxDynamicSharedMemorySize, GEMM_SMEM);
    cudaFuncSetAttribute(attn_h16,    cudaFuncAttributeMaxDynamicSharedMemorySize, ATTH_SMEM);

    __half *p_xn_h, *p_x1_h, *p_tokens_h, *p_q_h, *p_k_h, *p_v_h, *p_attn_h, *p_h_h, *p_mlp_h;
    __half *p_wq, *p_wk, *p_wv, *p_wp, *p_w1, *p_w2;
    uint32_t* p_mbits;
    cudaGetSymbolAddress((void**)&p_xn_h,     g_xn_h);
    cudaGetSymbolAddress((void**)&p_x1_h,     g_x1_h);
    cudaGetSymbolAddress((void**)&p_tokens_h, g_tokens_h);
    cudaGetSymbolAddress((void**)&p_q_h,      g_q_h);
    cudaGetSymbolAddress((void**)&p_k_h,      g_k_h);
    cudaGetSymbolAddress((void**)&p_v_h,      g_v_h);
    cudaGetSymbolAddress((void**)&p_attn_h,   g_attn_h);
    cudaGetSymbolAddress((void**)&p_h_h,      g_h_h);
    cudaGetSymbolAddress((void**)&p_mlp_h,    g_mlp_h);
    cudaGetSymbolAddress((void**)&p_wq,       g_wq_h);
    cudaGetSymbolAddress((void**)&p_wk,       g_wk_h);
    cudaGetSymbolAddress((void**)&p_wv,       g_wv_h);
    cudaGetSymbolAddress((void**)&p_wp,       g_wp_h);
    cudaGetSymbolAddress((void**)&p_w1,       g_w1_h);
    cudaGetSymbolAddress((void**)&p_w2,       g_w2_h);
    cudaGetSymbolAddress((void**)&p_mbits,    g_mbits);

    const int Mq = BB * NN;     // 16384
    const int Mt = BB * NL;     // 21392
    const int MqT = (Mq + 127) / 128;   // 128
    const int MtT = (Mt + 127) / 128;   // 168

    // 1) fused pre-pass: weight converts + LN1 + color copy + mask pack
    pre_kernel<<<PRE_GRID, 256>>>(x, ln1_g, ln1_b, ce, mask, Wq, Wk, Wv, Wp, W1, W2);

    // 2) fused Q + K + V GEMM (grid.x = 3 col segments)
    gemm_h<0,2><<<dim3(3 * (CC / 128), MtT), 256, GEMM_SMEM>>>(
        p_tokens_h, p_xn_h, p_wq, bq, p_wk, bk, p_wv, bv,
        nullptr, nullptr, p_q_h, p_k_h, p_v_h, Mt, Mq, CC, CC);

    // 3) fp16 flash attention -> attn_h
    attn_h16<<<dim3(NN / 128, HH, BB), 256, ATTH_SMEM>>>(p_mbits);

    // 4) x1 = xn + (attn @ Wp + bp)   (fp16 out)
    gemm_h<1,0><<<dim3(CC / 128, MqT), 256, GEMM_SMEM>>>(
        p_attn_h, nullptr, p_wp, bp, nullptr, nullptr, nullptr, nullptr,
        p_xn_h, nullptr, p_x1_h, nullptr, nullptr, Mq, 0, CC, CC);

    // 5) h = LN2(x1_h) -> h_h (fp16)
    ln_kernel<<<Mq, 256>>>(p_x1_h, ln2_g, ln2_b, p_h_h);

    // 6) mlp = gelu(h @ W1 + b1) -> fp16
    gemm_h<2,0><<<dim3(MLPD / 128, MqT), 256, GEMM_SMEM>>>(
        p_h_h, nullptr, p_w1, b1, nullptr, nullptr, nullptr, nullptr,
        nullptr, nullptr, p_mlp_h, nullptr, nullptr, Mq, 0, CC, MLPD);

    // 7) out = x1 + (mlp @ W2 + b2)   (fp16 res, fp32 out)
    gemm_h<1,0><<<dim3(CC / 128, MqT), 256, GEMM_SMEM>>>(
        p_mlp_h, nullptr, p_w2, b2, nullptr, nullptr, nullptr, nullptr,
        p_x1_h, out, nullptr, nullptr, nullptr, Mq, 0, MLPD, CC);
}